// round 10
// baseline (speedup 1.0000x reference)
#include <cuda_runtime.h>
#include <cuda_bf16.h>
#include <cstdint>

// Problem constants: outputs [64,512,1000] f32, labels [64,512] i32
#define LBL 1000

__device__ __align__(16) int g_first[1024];     // static zero-init; block 0 re-zeros
__device__ __align__(16) int g_argm_ev[1024];   // argmax of each label's first row
__device__ __align__(16) int g_idx[1024];       // pinv (inverse permutation)
__device__ unsigned g_ctr1, g_ctr2, g_flag;     // monotonic counters (replay-safe)

static __device__ __forceinline__ uint32_t smem_u32(const void* p) {
    uint32_t a;
    asm("{ .reg .u64 t; cvta.to.shared.u64 t, %1; cvt.u32.u64 %0, t; }"
        : "=r"(a) : "l"(p));
    return a;
}

// grid barrier on a monotonic counter, runtime grid size G (replay-safe)
static __device__ __forceinline__ void bar_full(unsigned* c, unsigned G) {
    __syncthreads();
    if (threadIdx.x == 0) {
        __threadfence();
        unsigned my  = atomicAdd(c, 1u);
        unsigned tgt = my - (my % G) + G;
        while (*(volatile unsigned*)c < tgt) { }
    }
    __syncthreads();
}
static __device__ __forceinline__ void bar_arrive(unsigned* c) {
    __syncthreads();
    if (threadIdx.x == 0) { __threadfence(); atomicAdd(c, 1u); }
}
static __device__ __forceinline__ void bar_wait(unsigned* c, unsigned G) {
    __syncthreads();
    if (threadIdx.x == 0) {
        __threadfence();
        unsigned my  = atomicAdd(c, 1u);
        unsigned tgt = my - (my % G) + G;
        while (*(volatile unsigned*)c < tgt) { }
    }
    __syncthreads();
}

struct GthSm {                       // gather view of the smem union
    int4  sidx[250];
    float srow[8][1024];             // 4 KB slab per warp (16B aligned)
};
struct ScnSm {                       // scan view
    unsigned  sbit[1024];
    int       sexc[1024];
    long long ev[1088];
    int       pinv[1024];
    int       stamp[1024];
    int       wsum[8];
    int       sE;
};
union SmU { GthSm g; ScnSm s; };

// ---------------------------------------------------------------------------
// ONE persistent kernel: first-occurrence + event argmax + speculative scan
// (block 0) overlapped with register prefetch + spin (other blocks), then a
// persistent TMA-store gather by everyone.
// ---------------------------------------------------------------------------
__global__ __launch_bounds__(256) void k_all(const float* __restrict__ in,
                                             const int* __restrict__ labels,
                                             float* __restrict__ out,
                                             int N, unsigned G) {
    __shared__ SmU u;
    __shared__ unsigned s_base;

    int t    = threadIdx.x;
    int lane = t & 31;
    int wid  = t >> 5;
    int bid  = blockIdx.x;

    if (t == 0) s_base = *(volatile unsigned*)&g_flag;   // flag epoch base

    // ---- Phase 1: first occurrence per label (encoded max(N-i); empty=0) --
    for (int i = bid * 256 + t; i < N; i += (int)G * 256)
        atomicMax(&g_first[labels[i]], N - i);

    bar_full(&g_ctr1, G);

    // ---- Phase 2: argmax of each label's first-occurrence row -------------
    int W = bid * 8 + wid;                       // G*8 >= 1184 warps >= LBL
    if (W < LBL) {
        int enc = __ldcg(&g_first[W]);
        if (enc > 0) {
            int row = N - enc;
            const float4* rp = reinterpret_cast<const float4*>(in) + (size_t)row * 250;
            float bv = -3.402823466e38f;
            int   bi = 0;
#pragma unroll
            for (int it = 0; it < 7; ++it) {
                int k = lane + it * 32;
                float4 vv = rp[k];
                int b = k * 4;
                if (vv.x > bv) { bv = vv.x; bi = b;     }
                if (vv.y > bv) { bv = vv.y; bi = b + 1; }
                if (vv.z > bv) { bv = vv.z; bi = b + 2; }
                if (vv.w > bv) { bv = vv.w; bi = b + 3; }
            }
            if (lane < 26) {
                int k = lane + 224;
                float4 vv = rp[k];
                int b = k * 4;
                if (vv.x > bv) { bv = vv.x; bi = b;     }
                if (vv.y > bv) { bv = vv.y; bi = b + 1; }
                if (vv.z > bv) { bv = vv.z; bi = b + 2; }
                if (vv.w > bv) { bv = vv.w; bi = b + 3; }
            }
#pragma unroll
            for (int off = 16; off > 0; off >>= 1) {
                float ov = __shfl_down_sync(0xFFFFFFFFu, bv, off);
                int   oi = __shfl_down_sync(0xFFFFFFFFu, bi, off);
                if (ov > bv || (ov == bv && oi < bi)) { bv = ov; bi = oi; }
            }
            if (lane == 0) g_argm_ev[W] = bi;
        }
    }

    // ---- Prefetch this warp's FIRST gather row (overlaps the scan) --------
    int row0 = bid * 8 + wid;
    float4 v[8];
    bool havev = (row0 < N);
    if (havev) {
        const float4* rp = reinterpret_cast<const float4*>(in + (size_t)row0 * 1000);
#pragma unroll
        for (int it = 0; it < 8; ++it) {
            int k = lane + it * 32;
            if (k < 250) v[it] = __ldcs(&rp[k]);
        }
    }

    if (bid != 0) {
        bar_arrive(&g_ctr2);
        if (t == 0) {                              // spin until scan publishes
            while (*(volatile unsigned*)&g_flag == s_base) { }
        }
        __syncthreads();
        __threadfence();
    } else {
        bar_wait(&g_ctr2, G);

        // ---- Phase A: rank events by row (bitmap + popc prefix, 256 thr) --
        for (int j = t; j < 1024; j += 256) {
            u.s.sbit[j] = 0u; u.s.pinv[j] = j; u.s.stamp[j] = 63;
        }
        for (int j = t; j < 1088; j += 256)
            u.s.ev[j] = ((long long)1023 << 32) | 1023u;
        int myf4[4];
#pragma unroll
        for (int q = 0; q < 4; ++q) {
            int l = t + q * 256;
            int e = (l < LBL) ? __ldcg(&g_first[l]) : 0;
            g_first[l] = 0;                        // reset for next replay
            myf4[q] = (e > 0) ? (N - e) : -1;
        }
        __syncthreads();
#pragma unroll
        for (int q = 0; q < 4; ++q)
            if (myf4[q] >= 0)
                atomicOr(&u.s.sbit[myf4[q] >> 5], 1u << (myf4[q] & 31));
        __syncthreads();

        int c4[4], csum = 0;
#pragma unroll
        for (int q = 0; q < 4; ++q) {
            c4[q] = __popc(u.s.sbit[t * 4 + q]);
            csum += c4[q];
        }
        int x = csum;
#pragma unroll
        for (int o = 1; o < 32; o <<= 1) {
            int y = __shfl_up_sync(0xFFFFFFFFu, x, o);
            if (lane >= o) x += y;
        }
        if (lane == 31) u.s.wsum[wid] = x;
        __syncthreads();
        if (t == 0) {
            int run = 0;
            for (int i = 0; i < 8; ++i) { int tmp = u.s.wsum[i]; u.s.wsum[i] = run; run += tmp; }
            u.s.sE = run;
        }
        __syncthreads();
        int ex = u.s.wsum[wid] + (x - csum);
#pragma unroll
        for (int q = 0; q < 4; ++q) { u.s.sexc[t * 4 + q] = ex; ex += c4[q]; }
        __syncthreads();
#pragma unroll
        for (int q = 0; q < 4; ++q) {
            int myf = myf4[q];
            if (myf >= 0) {
                int l = t + q * 256;
                unsigned wv = u.s.sbit[myf >> 5];
                int rank = u.s.sexc[myf >> 5] + __popc(wv & ((1u << (myf & 31)) - 1u));
                u.s.ev[rank] = ((long long)__ldcg(&g_argm_ev[l]) << 32) | (unsigned)l;
            }
        }
        __syncthreads();

        // ---- Phase B: warp-speculative batch scan (warp 0) ----------------
        if (t < 32) {
            const unsigned FULL = 0xFFFFFFFFu;
            int E = u.s.sE;
            int base = 0;
            while (base < E) {
                long long ee = u.s.ev[base + lane];
                int m   = (int)(ee >> 32);
                int lab = (int)(ee & 0xFFFFFFFFLL);
                int r   = u.s.pinv[m];
                int pl  = u.s.pinv[lab];
                int pr  = u.s.pinv[r];
                atomicMin(&u.s.stamp[r],   lane);
                atomicMin(&u.s.stamp[lab], lane);
                __syncwarp(FULL);
                int hz = (u.s.stamp[m] < lane) | (u.s.stamp[r] < lane) |
                         (u.s.stamp[lab] < lane);
                unsigned bal = __ballot_sync(FULL, hz);
                int f = bal ? (__ffs(bal) - 1) : 32;
                u.s.stamp[r]   = 63;
                u.s.stamp[lab] = 63;
                if (lane < f) { u.s.pinv[r] = pl; u.s.pinv[lab] = pr; }
                __syncwarp(FULL);
                base += f;
            }
        }
        __syncthreads();

        for (int j = t; j < LBL; j += 256) g_idx[j] = u.s.pinv[j];
        __threadfence();
        __syncthreads();
        if (t == 0) atomicAdd(&g_flag, 1u);        // release the gathers
    }

    // ---- Persistent gather: out[n, pinv[k]] = in[n, k] ---------------------
    if (t < 250)
        u.g.sidx[t] = __ldcg(reinterpret_cast<const int4*>(g_idx) + t);
    __syncthreads();

    int ngroups = (N + 7) >> 3;
    for (int g = bid; g < ngroups; g += (int)G) {
        int row = g * 8 + wid;
        if (!havev && row < N) {                   // loads overlap prev TMA drain
            const float4* rp = reinterpret_cast<const float4*>(in + (size_t)row * 1000);
#pragma unroll
            for (int it = 0; it < 8; ++it) {
                int k = lane + it * 32;
                if (k < 250) v[it] = __ldcs(&rp[k]);
            }
        }
        if (lane == 0)                              // slab free before reuse
            asm volatile("cp.async.bulk.wait_group 0;" ::: "memory");
        __syncwarp();
        if (row < N) {
            float* my = &u.g.srow[wid][0];
#pragma unroll
            for (int it = 0; it < 8; ++it) {
                int k = lane + it * 32;
                if (k < 250) {
                    int4 p = u.g.sidx[k];
                    my[p.x] = v[it].x;              // permuted scatter into smem
                    my[p.y] = v[it].y;
                    my[p.z] = v[it].z;
                    my[p.w] = v[it].w;
                }
            }
            asm volatile("fence.proxy.async.shared::cta;" ::: "memory");
            __syncwarp();
            if (lane == 0) {
                uint32_t saddr = smem_u32(my);
                float*   gdst  = out + (size_t)row * 1000;
                asm volatile(
                    "cp.async.bulk.global.shared::cta.bulk_group [%0], [%1], %2;"
                    :: "l"(gdst), "r"(saddr), "r"(4000) : "memory");
                asm volatile("cp.async.bulk.commit_group;" ::: "memory");
            }
        }
        havev = false;
    }
    // smem must stay alive until all bulk stores drain
    if (lane == 0)
        asm volatile("cp.async.bulk.wait_group 0;" ::: "memory");
}

// ---------------------------------------------------------------------------
extern "C" void kernel_launch(void* const* d_in, const int* in_sizes, int n_in,
                              void* d_out, int out_size) {
    const float* in     = (const float*)d_in[0];
    const int*   labels = (const int*)d_in[1];
    float*       out    = (float*)d_out;
    int N = in_sizes[1];   // 32768 rows; L = 1000

    static int G = 0;      // occupancy-derived co-resident grid (host query)
    if (!G) {
        int dev = 0, nsm = 0, nb = 0;
        cudaGetDevice(&dev);
        cudaDeviceGetAttribute(&nsm, cudaDevAttrMultiProcessorCount, dev);
        cudaOccupancyMaxActiveBlocksPerMultiprocessor(&nb, k_all, 256, 0);
        if (nb < 1) nb = 1;
        G = nb * nsm;
    }
    k_all<<<G, 256>>>(in, labels, out, N, (unsigned)G);
}

// round 11
// speedup vs baseline: 1.0047x; 1.0047x over previous
#include <cuda_runtime.h>
#include <cuda_bf16.h>
#include <cstdint>

// Problem constants: outputs [64,512,1000] f32, labels [64,512] i32
#define LBL 1000

__device__ __align__(16) int g_first[1024];     // static zero-init; block 0 re-zeros
__device__ __align__(16) int g_argm_ev[1024];   // argmax of each label's first row
__device__ __align__(16) int g_idx[1024];       // pinv (inverse permutation)
__device__ unsigned g_ctr1, g_ctr2, g_flag;     // monotonic counters (replay-safe)

static __device__ __forceinline__ uint32_t smem_u32(const void* p) {
    uint32_t a;
    asm("{ .reg .u64 t; cvta.to.shared.u64 t, %1; cvt.u32.u64 %0, t; }"
        : "=r"(a) : "l"(p));
    return a;
}

// grid barrier on a monotonic counter, runtime grid size G (replay-safe)
static __device__ __forceinline__ void bar_full(unsigned* c, unsigned G) {
    __syncthreads();
    if (threadIdx.x == 0) {
        __threadfence();
        unsigned my  = atomicAdd(c, 1u);
        unsigned tgt = my - (my % G) + G;
        while (*(volatile unsigned*)c < tgt) { }
    }
    __syncthreads();
}
static __device__ __forceinline__ void bar_arrive(unsigned* c) {
    __syncthreads();
    if (threadIdx.x == 0) { __threadfence(); atomicAdd(c, 1u); }
}
static __device__ __forceinline__ void bar_wait(unsigned* c, unsigned G) {
    __syncthreads();
    if (threadIdx.x == 0) {
        __threadfence();
        unsigned my  = atomicAdd(c, 1u);
        unsigned tgt = my - (my % G) + G;
        while (*(volatile unsigned*)c < tgt) { }
    }
    __syncthreads();
}

struct GthSm {                       // gather view of the smem union
    int4  sidx[250];
    float srow[8][1008];             // 4032 B slab per warp (16B aligned)
};
struct ScnSm {                       // scan view
    unsigned  sbit[1024];
    int       sexc[1024];
    long long ev[1088];
    int       pinv[1024];
    int       stamp[1024];
    int       wsum[8];
    int       sE;
};
union SmU { GthSm g; ScnSm s; };

// ---------------------------------------------------------------------------
// ONE persistent kernel. 5 blocks/SM (gather-grade occupancy):
//   phase1 first-occurrence -> bar -> phase2 event argmax ->
//   block 0: spec scan;  others: L2-prefetch their upcoming gather tiles
//   while polling the publish flag;  then everyone: TMA-store gather.
// ---------------------------------------------------------------------------
__global__ __launch_bounds__(256, 5) void k_all(const float* __restrict__ in,
                                                const int* __restrict__ labels,
                                                float* __restrict__ out,
                                                int N, unsigned G) {
    __shared__ SmU u;
    __shared__ unsigned s_base;
    __shared__ int s_go;

    int t    = threadIdx.x;
    int lane = t & 31;
    int wid  = t >> 5;
    int bid  = blockIdx.x;
    int ngroups = (N + 7) >> 3;

    if (t == 0) s_base = *(volatile unsigned*)&g_flag;   // flag epoch base

    // ---- Phase 1: first occurrence per label (encoded max(N-i); empty=0) --
    for (int i = bid * 256 + t; i < N; i += (int)G * 256)
        atomicMax(&g_first[labels[i]], N - i);

    bar_full(&g_ctr1, G);

    // ---- Phase 2: argmax of each label's first-occurrence row -------------
    int W = bid * 8 + wid;                       // G*8 >= LBL warps
    if (W < LBL) {
        int enc = __ldcg(&g_first[W]);
        if (enc > 0) {
            int row = N - enc;
            const float4* rp = reinterpret_cast<const float4*>(in) + (size_t)row * 250;
            float bv = -3.402823466e38f;
            int   bi = 0;
#pragma unroll
            for (int it = 0; it < 7; ++it) {
                int k = lane + it * 32;
                float4 vv = rp[k];
                int b = k * 4;
                if (vv.x > bv) { bv = vv.x; bi = b;     }
                if (vv.y > bv) { bv = vv.y; bi = b + 1; }
                if (vv.z > bv) { bv = vv.z; bi = b + 2; }
                if (vv.w > bv) { bv = vv.w; bi = b + 3; }
            }
            if (lane < 26) {
                int k = lane + 224;
                float4 vv = rp[k];
                int b = k * 4;
                if (vv.x > bv) { bv = vv.x; bi = b;     }
                if (vv.y > bv) { bv = vv.y; bi = b + 1; }
                if (vv.z > bv) { bv = vv.z; bi = b + 2; }
                if (vv.w > bv) { bv = vv.w; bi = b + 3; }
            }
#pragma unroll
            for (int off = 16; off > 0; off >>= 1) {
                float ov = __shfl_down_sync(0xFFFFFFFFu, bv, off);
                int   oi = __shfl_down_sync(0xFFFFFFFFu, bi, off);
                if (ov > bv || (ov == bv && oi < bi)) { bv = ov; bi = oi; }
            }
            if (lane == 0) g_argm_ev[W] = bi;
        }
    }

    if (bid != 0) {
        bar_arrive(&g_ctr2);
        // ---- L2-prefetch own upcoming tiles while polling the flag --------
        int pfg = bid;                         // consumption order: bid, bid+G,..
        float acc = 0.f;
        for (;;) {
            if (t == 0) s_go = (*(volatile unsigned*)&g_flag != s_base);
            __syncthreads();
            if (s_go) break;
            if (pfg < ngroups) {
                int row = pfg * 8 + wid;
                if (row < N) {
                    const float4* rp =
                        reinterpret_cast<const float4*>(in + (size_t)row * 1000);
#pragma unroll
                    for (int it = 0; it < 8; ++it) {
                        int k = lane + it * 32;
                        if (k < 250) {
                            float4 x4 = __ldcg(&rp[k]);   // L2 fill, value dropped
                            acc += x4.x + x4.y + x4.z + x4.w;
                        }
                    }
                }
                pfg += (int)G;
            }
            __syncthreads();                   // t0's next s_go write can't race
        }
        asm volatile("" :: "f"(acc));
        __threadfence();
    } else {
        bar_wait(&g_ctr2, G);

        // ---- Phase A: rank events by row (bitmap + popc prefix, 256 thr) --
        for (int j = t; j < 1024; j += 256) {
            u.s.sbit[j] = 0u; u.s.pinv[j] = j; u.s.stamp[j] = 63;
        }
        for (int j = t; j < 1088; j += 256)
            u.s.ev[j] = ((long long)1023 << 32) | 1023u;
        int myf4[4];
#pragma unroll
        for (int q = 0; q < 4; ++q) {
            int l = t + q * 256;
            int e = (l < LBL) ? __ldcg(&g_first[l]) : 0;
            g_first[l] = 0;                    // reset for next replay
            myf4[q] = (e > 0) ? (N - e) : -1;
        }
        __syncthreads();
#pragma unroll
        for (int q = 0; q < 4; ++q)
            if (myf4[q] >= 0)
                atomicOr(&u.s.sbit[myf4[q] >> 5], 1u << (myf4[q] & 31));
        __syncthreads();

        int c4[4], csum = 0;
#pragma unroll
        for (int q = 0; q < 4; ++q) {
            c4[q] = __popc(u.s.sbit[t * 4 + q]);
            csum += c4[q];
        }
        int x = csum;
#pragma unroll
        for (int o = 1; o < 32; o <<= 1) {
            int y = __shfl_up_sync(0xFFFFFFFFu, x, o);
            if (lane >= o) x += y;
        }
        if (lane == 31) u.s.wsum[wid] = x;
        __syncthreads();
        if (t == 0) {
            int run = 0;
            for (int i = 0; i < 8; ++i) { int tmp = u.s.wsum[i]; u.s.wsum[i] = run; run += tmp; }
            u.s.sE = run;
        }
        __syncthreads();
        int ex = u.s.wsum[wid] + (x - csum);
#pragma unroll
        for (int q = 0; q < 4; ++q) { u.s.sexc[t * 4 + q] = ex; ex += c4[q]; }
        __syncthreads();
#pragma unroll
        for (int q = 0; q < 4; ++q) {
            int myf = myf4[q];
            if (myf >= 0) {
                int l = t + q * 256;
                unsigned wv = u.s.sbit[myf >> 5];
                int rank = u.s.sexc[myf >> 5] + __popc(wv & ((1u << (myf & 31)) - 1u));
                u.s.ev[rank] = ((long long)__ldcg(&g_argm_ev[l]) << 32) | (unsigned)l;
            }
        }
        __syncthreads();

        // ---- Phase B: warp-speculative batch scan (warp 0) ----------------
        if (t < 32) {
            const unsigned FULL = 0xFFFFFFFFu;
            int E = u.s.sE;
            int base = 0;
            while (base < E) {
                long long ee = u.s.ev[base + lane];
                int m   = (int)(ee >> 32);
                int lab = (int)(ee & 0xFFFFFFFFLL);
                int r   = u.s.pinv[m];
                int pl  = u.s.pinv[lab];
                int pr  = u.s.pinv[r];
                atomicMin(&u.s.stamp[r],   lane);
                atomicMin(&u.s.stamp[lab], lane);
                __syncwarp(FULL);
                int hz = (u.s.stamp[m] < lane) | (u.s.stamp[r] < lane) |
                         (u.s.stamp[lab] < lane);
                unsigned bal = __ballot_sync(FULL, hz);
                int f = bal ? (__ffs(bal) - 1) : 32;
                u.s.stamp[r]   = 63;
                u.s.stamp[lab] = 63;
                if (lane < f) { u.s.pinv[r] = pl; u.s.pinv[lab] = pr; }
                __syncwarp(FULL);
                base += f;
            }
        }
        __syncthreads();

        for (int j = t; j < LBL; j += 256) g_idx[j] = u.s.pinv[j];
        __threadfence();
        __syncthreads();
        if (t == 0) atomicAdd(&g_flag, 1u);        // release the gathers
    }

    // ---- Persistent gather: out[n, pinv[k]] = in[n, k] ---------------------
    if (t < 250)
        u.g.sidx[t] = __ldcg(reinterpret_cast<const int4*>(g_idx) + t);
    __syncthreads();

    for (int g = bid; g < ngroups; g += (int)G) {
        int row = g * 8 + wid;
        float4 v[8];
        if (row < N) {
            const float4* rp = reinterpret_cast<const float4*>(in + (size_t)row * 1000);
#pragma unroll
            for (int it = 0; it < 8; ++it) {
                int k = lane + it * 32;
                if (k < 250) v[it] = __ldcs(&rp[k]);   // loads overlap TMA drain
            }
        }
        if (lane == 0)                              // slab free before reuse
            asm volatile("cp.async.bulk.wait_group 0;" ::: "memory");
        __syncwarp();
        if (row < N) {
            float* my = &u.g.srow[wid][0];
#pragma unroll
            for (int it = 0; it < 8; ++it) {
                int k = lane + it * 32;
                if (k < 250) {
                    int4 p = u.g.sidx[k];
                    my[p.x] = v[it].x;              // permuted scatter into smem
                    my[p.y] = v[it].y;
                    my[p.z] = v[it].z;
                    my[p.w] = v[it].w;
                }
            }
            asm volatile("fence.proxy.async.shared::cta;" ::: "memory");
            __syncwarp();
            if (lane == 0) {
                uint32_t saddr = smem_u32(my);
                float*   gdst  = out + (size_t)row * 1000;
                asm volatile(
                    "cp.async.bulk.global.shared::cta.bulk_group [%0], [%1], %2;"
                    :: "l"(gdst), "r"(saddr), "r"(4000) : "memory");
                asm volatile("cp.async.bulk.commit_group;" ::: "memory");
            }
        }
    }
    // smem must stay alive until all bulk stores drain
    if (lane == 0)
        asm volatile("cp.async.bulk.wait_group 0;" ::: "memory");
}

// ---------------------------------------------------------------------------
extern "C" void kernel_launch(void* const* d_in, const int* in_sizes, int n_in,
                              void* d_out, int out_size) {
    const float* in     = (const float*)d_in[0];
    const int*   labels = (const int*)d_in[1];
    float*       out    = (float*)d_out;
    int N = in_sizes[1];   // 32768 rows; L = 1000

    static int G = 0;      // occupancy-derived co-resident grid (host query)
    if (!G) {
        int dev = 0, nsm = 0, nb = 0;
        cudaGetDevice(&dev);
        cudaDeviceGetAttribute(&nsm, cudaDevAttrMultiProcessorCount, dev);
        cudaOccupancyMaxActiveBlocksPerMultiprocessor(&nb, k_all, 256, 0);
        if (nb < 1) nb = 1;
        G = nb * nsm;
    }
    k_all<<<G, 256>>>(in, labels, out, N, (unsigned)G);
}

// round 12
// speedup vs baseline: 1.0471x; 1.0422x over previous
#include <cuda_runtime.h>
#include <cuda_bf16.h>
#include <cstdint>

// Problem constants: outputs [64,512,1000] f32, labels [64,512] i32
#define LBL 1000

__device__ __align__(16) int g_first[1024];     // static zero-init; k_scan re-zeros
__device__ __align__(16) int g_argm_ev[1024];   // argmax of each label's first row
__device__ __align__(16) int g_idx[1024];       // pinv (inverse permutation)

static __device__ __forceinline__ uint32_t smem_u32(const void* p) {
    uint32_t a;
    asm("{ .reg .u64 t; cvta.to.shared.u64 t, %1; cvt.u32.u64 %0, t; }"
        : "=r"(a) : "l"(p));
    return a;
}

// ---------------------------------------------------------------------------
// K0: first occurrence per label, from labels only.
// Encoded as max(N - i) so the empty state is 0 (static zero init, no reset
// kernel; k_scan re-zeros after consuming). 32768 atomics over 1000 addrs.
// ---------------------------------------------------------------------------
__global__ __launch_bounds__(256) void k_first(const int* __restrict__ labels,
                                               int N) {
    int i = blockIdx.x * blockDim.x + threadIdx.x;
    if (i < N) atomicMax(&g_first[labels[i]], N - i);
}

// ---------------------------------------------------------------------------
// K1: argmax of ONLY the first-occurrence rows (<=1000 rows, ~4 MB).
// One warp per label. PDL: dispatched under k_first, syncs at top.
// ---------------------------------------------------------------------------
__global__ __launch_bounds__(256) void k_argmax_ev(const float* __restrict__ in,
                                                   int N) {
    cudaGridDependencySynchronize();             // wait k_first (PDL)

    int t    = (blockIdx.x * blockDim.x + threadIdx.x) >> 5;   // label id
    int lane = threadIdx.x & 31;
    if (t >= LBL) return;
    int enc = g_first[t];
    if (enc <= 0) return;            // label never occurs
    int row = N - enc;               // first-occurrence row

    const float4* rp = reinterpret_cast<const float4*>(in) + (size_t)row * 250;
    float bv = -3.402823466e38f;
    int   bi = 0;
#pragma unroll
    for (int it = 0; it < 7; ++it) {             // k = lane + 32*it <= 223
        int k = lane + it * 32;
        float4 v = rp[k];
        int b = k * 4;
        if (v.x > bv) { bv = v.x; bi = b;     }
        if (v.y > bv) { bv = v.y; bi = b + 1; }
        if (v.z > bv) { bv = v.z; bi = b + 2; }
        if (v.w > bv) { bv = v.w; bi = b + 3; }
    }
    if (lane < 26) {                              // tail: k = lane + 224 < 250
        int k = lane + 224;
        float4 v = rp[k];
        int b = k * 4;
        if (v.x > bv) { bv = v.x; bi = b;     }
        if (v.y > bv) { bv = v.y; bi = b + 1; }
        if (v.z > bv) { bv = v.z; bi = b + 2; }
        if (v.w > bv) { bv = v.w; bi = b + 3; }
    }
#pragma unroll
    for (int off = 16; off > 0; off >>= 1) {
        float ov = __shfl_down_sync(0xFFFFFFFFu, bv, off);
        int   oi = __shfl_down_sync(0xFFFFFFFFu, bi, off);
        if (ov > bv || (ov == bv && oi < bi)) { bv = ov; bi = oi; }
    }
    if (lane == 0) g_argm_ev[t] = bi;
}

// ---------------------------------------------------------------------------
// K2: single block. PDL: smem init runs under k_argmax_ev, sync before
// reading g_first / g_argm_ev.
//   Phase A: rank events by row via 32768-bit bitmap + popc prefix-sum.
//   Phase B: warp-speculative batch scan (warp 0).
//   Output: g_idx = pinv directly (gather scatters with pinv).
// ---------------------------------------------------------------------------
__global__ __launch_bounds__(1024) void k_scan(int N) {
    __shared__ unsigned  sbit[1024];   // 32768-bit row bitmap
    __shared__ int       sexc[1024];   // exclusive popc prefix per word
    __shared__ long long ev[1088];     // packed (m << 32) | lab, sorted by row
    __shared__ int       pinv[1024];
    __shared__ int       stamp[1024];  // per-cell lane stamps for hazard detect
    __shared__ int       wsum[32];
    __shared__ int       sE;

    int t = threadIdx.x;
    int lane = t & 31, w = t >> 5;

    // ---- prework (independent of predecessors) ----------------------------
    sbit[t]  = 0u;
    pinv[t]  = t;
    stamp[t] = 63;
    ev[t]    = ((long long)1023 << 32) | 1023u;     // dummy everywhere
    if (t < 64) ev[1024 + t] = ((long long)1023 << 32) | 1023u;

    cudaGridDependencySynchronize();   // wait k_argmax_ev (PDL, transitive)

    int enc = (t < LBL) ? g_first[t] : 0;
    g_first[t] = 0;                    // reset for next graph replay
    int myf = (enc > 0) ? (N - enc) : -1;
    __syncthreads();

    if (myf >= 0)
        atomicOr(&sbit[myf >> 5], 1u << (myf & 31));
    __syncthreads();

    // block prefix-sum of per-word popcounts
    unsigned word = sbit[t];
    int c = __popc(word);
    int x = c;
#pragma unroll
    for (int o = 1; o < 32; o <<= 1) {
        int y = __shfl_up_sync(0xFFFFFFFFu, x, o);
        if (lane >= o) x += y;
    }
    if (lane == 31) wsum[w] = x;
    __syncthreads();
    if (t < 32) {
        int v = wsum[t];
        int iv = v;
#pragma unroll
        for (int o = 1; o < 32; o <<= 1) {
            int y = __shfl_up_sync(0xFFFFFFFFu, iv, o);
            if (t >= o) iv += y;
        }
        wsum[t] = iv - v;          // exclusive warp offset
        if (t == 31) sE = iv;      // total number of events
    }
    __syncthreads();
    sexc[t] = wsum[w] + (x - c);
    __syncthreads();

    if (myf >= 0) {
        unsigned wv = sbit[myf >> 5];
        int rank = sexc[myf >> 5] + __popc(wv & ((1u << (myf & 31)) - 1u));
        ev[rank] = ((long long)g_argm_ev[t] << 32) | (unsigned)t;
    }
    __syncthreads();

    // Phase B: warp-speculative batch loop (warp 0 only)
    if (t < 32) {
        const unsigned FULL = 0xFFFFFFFFu;
        int E = sE;
        int base = 0;
        while (base < E) {
            long long ee = ev[base + lane];
            int m   = (int)(ee >> 32);
            int lab = (int)(ee & 0xFFFFFFFFLL);
            int r   = pinv[m];                // speculative (round-start state)
            int pl  = pinv[lab];
            int pr  = pinv[r];
            atomicMin(&stamp[r],   lane);
            atomicMin(&stamp[lab], lane);
            __syncwarp(FULL);
            int hz = (stamp[m] < lane) | (stamp[r] < lane) | (stamp[lab] < lane);
            unsigned bal = __ballot_sync(FULL, hz);
            int f = bal ? (__ffs(bal) - 1) : 32;    // f >= 1 always (lane 0 safe)
            stamp[r]   = 63;                   // reset stamps (post-ballot sync)
            stamp[lab] = 63;
            if (lane < f) {                    // commit conflict-free prefix
                pinv[r]   = pl;
                pinv[lab] = pr;
            }
            __syncwarp(FULL);
            base += f;
        }
    }
    __syncthreads();

    if (t < LBL) g_idx[t] = pinv[t];   // store pinv directly (scatter gather)
}

// ---------------------------------------------------------------------------
// K3: out[n, pinv[k]] = in[n, k]. PDL: row LDGs (input-only, no g_idx needed)
// are issued BEFORE the dependency sync => wave-1 reads (~24 MB) overlap the
// whole scan chain. Then permuted scalar-STS scatter + TMA bulk store.
// ---------------------------------------------------------------------------
__global__ __launch_bounds__(256) void k_gather(const float* __restrict__ in,
                                                float* __restrict__ out, int N) {
    __shared__ int4 sidx[250];                       // pinv, packed
    __shared__ __align__(16) float srow[8][1000];    // 4 KB slab per warp

    int t    = threadIdx.x;
    int wid  = t >> 5;
    int lane = t & 31;

    // ---- prework: issue all row loads (overlaps k_scan via PDL) -----------
    int row = blockIdx.x * 8 + wid;
    float4 v[8];
    if (row < N) {
        const float4* rp = reinterpret_cast<const float4*>(in + (size_t)row * 1000);
#pragma unroll
        for (int it = 0; it < 8; ++it) {
            int k = lane + it * 32;
            if (k < 250) v[it] = __ldcs(&rp[k]);
        }
    }

    cudaGridDependencySynchronize();   // wait k_scan (PDL) -> g_idx ready

    if (t < 250) sidx[t] = reinterpret_cast<const int4*>(g_idx)[t];
    __syncthreads();

    if (row < N) {
        float* my = &srow[wid][0];
#pragma unroll
        for (int it = 0; it < 8; ++it) {
            int k = lane + it * 32;
            if (k < 250) {
                int4 p = sidx[k];
                my[p.x] = v[it].x;     // permuted scatter into smem
                my[p.y] = v[it].y;
                my[p.z] = v[it].z;
                my[p.w] = v[it].w;
            }
        }
        // order the generic STS above before the async-proxy smem reads
        asm volatile("fence.proxy.async.shared::cta;" ::: "memory");
        __syncwarp();
        if (lane == 0) {
            uint32_t saddr = smem_u32(my);
            float*   gdst  = out + (size_t)row * 1000;
            asm volatile(
                "cp.async.bulk.global.shared::cta.bulk_group [%0], [%1], %2;"
                :: "l"(gdst), "r"(saddr), "r"(4000) : "memory");
            asm volatile("cp.async.bulk.commit_group;" ::: "memory");
            asm volatile("cp.async.bulk.wait_group 0;" ::: "memory");
        }
        __syncwarp();
    }
}

// ---------------------------------------------------------------------------
// host: PDL launches (programmatic stream serialization on the capture stream)
// ---------------------------------------------------------------------------
template <typename F, typename... Args>
static void launch_pdl(F func, dim3 grid, dim3 block, Args... args) {
    cudaLaunchConfig_t cfg = {};
    cfg.gridDim  = grid;
    cfg.blockDim = block;
    cfg.dynamicSmemBytes = 0;
    cfg.stream = 0;                      // legacy default stream (captured)
    cudaLaunchAttribute attr[1];
    attr[0].id = cudaLaunchAttributeProgrammaticStreamSerialization;
    attr[0].val.programmaticStreamSerializationAllowed = 1;
    cfg.attrs = attr;
    cfg.numAttrs = 1;
    cudaLaunchKernelEx(&cfg, func, args...);
}

extern "C" void kernel_launch(void* const* d_in, const int* in_sizes, int n_in,
                              void* d_out, int out_size) {
    const float* in     = (const float*)d_in[0];
    const int*   labels = (const int*)d_in[1];
    float*       out    = (float*)d_out;
    int N = in_sizes[1];   // 32768 rows; L = 1000

    k_first<<<(N + 255) / 256, 256>>>(labels, N);
    launch_pdl(k_argmax_ev, dim3((LBL * 32 + 255) / 256), dim3(256), in, N);
    launch_pdl(k_scan,      dim3(1),                      dim3(1024), N);
    launch_pdl(k_gather,    dim3((N + 7) / 8),            dim3(256), in, out, N);
}